// round 1
// baseline (speedup 1.0000x reference)
#include <cuda_runtime.h>

#define DIM   1024
#define SEQ   2048
#define BATCH 2
#define NH    16
#define HD    64
#define MROWS (BATCH*SEQ)   /* 4096 */

/* ---------------- scratch (device globals: allocation-free) -------------- */
__device__ float g_qh[BATCH*NH*SEQ*HD];   /* [B,H,S,hd] */
__device__ float g_kh[BATCH*NH*SEQ*HD];
__device__ float g_vh[BATCH*NH*SEQ*HD];
__device__ float g_ao[MROWS*DIM];         /* [B*S, D]  attention output */

/* ---------------- SGEMM: C = A @ W^T  (A:[M,1024], W:[1024,1024]) -------- */
#define BM 128
#define BN 128
#define BK 16
#define BSTR 132   /* padded row stride of transposed W tile */

__device__ __forceinline__ void gemm_body(
    const float* __restrict__ A, const float* __restrict__ W,
    float* __restrict__ C, int headSplit,
    float* __restrict__ As, float* __restrict__ Bs)
{
    const int tid = threadIdx.x;
    const int m0 = blockIdx.y * BM;
    const int n0 = blockIdx.x * BN;
    const int ty = tid >> 4, tx = tid & 15;
    const int lr = tid >> 2;           /* 0..63 */
    const int lc = (tid & 3) << 2;     /* 0,4,8,12 */

    float acc[8][8];
#pragma unroll
    for (int i = 0; i < 8; i++)
#pragma unroll
        for (int j = 0; j < 8; j++) acc[i][j] = 0.f;

    for (int k0 = 0; k0 < DIM; k0 += BK) {
#pragma unroll
        for (int r = 0; r < BM; r += 64) {
            float4 v = *(const float4*)(A + (size_t)(m0 + lr + r) * DIM + k0 + lc);
            *(float4*)(As + (lr + r) * BK + lc) = v;
        }
#pragma unroll
        for (int r = 0; r < BN; r += 64) {
            float4 v = *(const float4*)(W + (size_t)(n0 + lr + r) * DIM + k0 + lc);
            Bs[(lc + 0) * BSTR + lr + r] = v.x;
            Bs[(lc + 1) * BSTR + lr + r] = v.y;
            Bs[(lc + 2) * BSTR + lr + r] = v.z;
            Bs[(lc + 3) * BSTR + lr + r] = v.w;
        }
        __syncthreads();
#pragma unroll
        for (int kk = 0; kk < BK; kk++) {
            float a[8], b[8];
#pragma unroll
            for (int i = 0; i < 8; i++) a[i] = As[(ty * 8 + i) * BK + kk];
#pragma unroll
            for (int j = 0; j < 8; j++) b[j] = Bs[kk * BSTR + tx * 8 + j];
#pragma unroll
            for (int i = 0; i < 8; i++)
#pragma unroll
                for (int j = 0; j < 8; j++)
                    acc[i][j] = fmaf(a[i], b[j], acc[i][j]);
        }
        __syncthreads();
    }

#pragma unroll
    for (int i = 0; i < 8; i++) {
        int m = m0 + ty * 8 + i;
        if (headSplit) {
            int b = m >> 11, s = m & (SEQ - 1);
#pragma unroll
            for (int j = 0; j < 8; j += 4) {
                int n = n0 + tx * 8 + j;
                int h = n >> 6, d = n & 63;
                float4 v = make_float4(acc[i][j], acc[i][j+1], acc[i][j+2], acc[i][j+3]);
                *(float4*)(C + ((size_t)((b * NH + h) * SEQ + s) << 6) + d) = v;
            }
        } else {
#pragma unroll
            for (int j = 0; j < 8; j += 4) {
                float4 v = make_float4(acc[i][j], acc[i][j+1], acc[i][j+2], acc[i][j+3]);
                *(float4*)(C + (size_t)m * DIM + n0 + tx * 8 + j) = v;
            }
        }
    }
}

/* fused QKV projection: blockIdx.z picks which of the three GEMMs */
__global__ __launch_bounds__(256) void gemm_qkv(
    const float* __restrict__ q, const float* __restrict__ k, const float* __restrict__ v,
    const float* __restrict__ wq, const float* __restrict__ wk, const float* __restrict__ wv,
    float* __restrict__ qh, float* __restrict__ kh, float* __restrict__ vh)
{
    __shared__ float As[BM * BK];
    __shared__ float Bs[BK * BSTR];
    const float* A; const float* W; float* C;
    if (blockIdx.z == 0)      { A = q; W = wq; C = qh; }
    else if (blockIdx.z == 1) { A = k; W = wk; C = kh; }
    else                      { A = v; W = wv; C = vh; }
    gemm_body(A, W, C, 1, As, Bs);
}

__global__ __launch_bounds__(256) void gemm_out(
    const float* __restrict__ A, const float* __restrict__ W, float* __restrict__ C)
{
    __shared__ float As[BM * BK];
    __shared__ float Bs[BK * BSTR];
    gemm_body(A, W, C, 0, As, Bs);
}

/* ---------------- flash attention (causal), 64x64 tiles, fp32 ------------ */
/* grid: x = q-tile (32), y = b*H+h (32); 256 threads (16x16), 4x4 micro    */
__global__ __launch_bounds__(256) void flash_attn(
    const float* __restrict__ Qh, const float* __restrict__ Kh,
    const float* __restrict__ Vh, float* __restrict__ AO)
{
    extern __shared__ float sm[];
    float* Qs = sm;            /* [64][64] rows scaled by 1/8  */
    float* Kt = sm + 4096;     /* [k][c] transposed key tile   */
    float* Vs = sm + 8192;     /* [c][d]                       */
    float* Ps = sm + 12288;    /* [r][c] probabilities         */

    const int bh = blockIdx.y;
    const int qt = blockIdx.x;
    const int q0 = qt * 64;
    const float* Qb = Qh + (size_t)bh * SEQ * HD;
    const float* Kb = Kh + (size_t)bh * SEQ * HD;
    const float* Vb = Vh + (size_t)bh * SEQ * HD;

    const int tid = threadIdx.x;
    const int ty = tid >> 4, tx = tid & 15;

    /* load Q tile, pre-scaled by 1/sqrt(hd) */
    for (int i4 = tid; i4 < 1024; i4 += 256) {
        int r = i4 >> 4, c4 = (i4 & 15) << 2;
        float4 v = *(const float4*)(Qb + (size_t)(q0 + r) * HD + c4);
        v.x *= 0.125f; v.y *= 0.125f; v.z *= 0.125f; v.w *= 0.125f;
        *(float4*)(Qs + r * 64 + c4) = v;
    }

    float m_i[4], l_i[4], acc[4][4];
#pragma unroll
    for (int i = 0; i < 4; i++) {
        m_i[i] = -1e30f; l_i[i] = 0.f;
#pragma unroll
        for (int j = 0; j < 4; j++) acc[i][j] = 0.f;
    }
    __syncthreads();

    for (int kt = 0; kt <= qt; kt++) {
        const int k0 = kt * 64;
        /* K: lane-per-row mapping -> conflict-free transposed STS */
        for (int i4 = tid; i4 < 1024; i4 += 256) {
            int r = i4 & 63, c4 = (i4 >> 6) << 2;
            float4 kv = *(const float4*)(Kb + (size_t)(k0 + r) * HD + c4);
            Kt[(c4 + 0) * 64 + r] = kv.x;
            Kt[(c4 + 1) * 64 + r] = kv.y;
            Kt[(c4 + 2) * 64 + r] = kv.z;
            Kt[(c4 + 3) * 64 + r] = kv.w;
        }
        /* V: contiguous */
        for (int i4 = tid; i4 < 1024; i4 += 256) {
            int r = i4 >> 4, c4 = (i4 & 15) << 2;
            *(float4*)(Vs + r * 64 + c4) =
                *(const float4*)(Vb + (size_t)(k0 + r) * HD + c4);
        }
        __syncthreads();

        /* scores S = Q K^T */
        float s[4][4];
#pragma unroll
        for (int i = 0; i < 4; i++)
#pragma unroll
            for (int j = 0; j < 4; j++) s[i][j] = 0.f;

#pragma unroll 8
        for (int k = 0; k < 64; k++) {
            float4 kk = *(const float4*)(Kt + k * 64 + tx * 4);
#pragma unroll
            for (int i = 0; i < 4; i++) {
                float qv = Qs[(ty * 4 + i) * 64 + k];
                s[i][0] = fmaf(qv, kk.x, s[i][0]);
                s[i][1] = fmaf(qv, kk.y, s[i][1]);
                s[i][2] = fmaf(qv, kk.z, s[i][2]);
                s[i][3] = fmaf(qv, kk.w, s[i][3]);
            }
        }

        if (kt == qt) {   /* diagonal tile: mask j > i (tile-local == global) */
#pragma unroll
            for (int i = 0; i < 4; i++)
#pragma unroll
                for (int j = 0; j < 4; j++)
                    if (tx * 4 + j > ty * 4 + i) s[i][j] = -1e30f;
        }

        /* online softmax per row (16 tx threads share a row group) */
#pragma unroll
        for (int i = 0; i < 4; i++) {
            float mx = fmaxf(fmaxf(s[i][0], s[i][1]), fmaxf(s[i][2], s[i][3]));
#pragma unroll
            for (int off = 8; off; off >>= 1)
                mx = fmaxf(mx, __shfl_xor_sync(0xffffffffu, mx, off));
            float mnew = fmaxf(m_i[i], mx);
            float corr = __expf(m_i[i] - mnew);
            float sum = 0.f;
#pragma unroll
            for (int j = 0; j < 4; j++) {
                float p = __expf(s[i][j] - mnew);
                s[i][j] = p; sum += p;
            }
#pragma unroll
            for (int off = 8; off; off >>= 1)
                sum += __shfl_xor_sync(0xffffffffu, sum, off);
            l_i[i] = l_i[i] * corr + sum;
            m_i[i] = mnew;
#pragma unroll
            for (int j = 0; j < 4; j++) acc[i][j] *= corr;
            *(float4*)(Ps + (ty * 4 + i) * 64 + tx * 4) =
                make_float4(s[i][0], s[i][1], s[i][2], s[i][3]);
        }
        __syncthreads();

        /* O += P V */
#pragma unroll 8
        for (int c = 0; c < 64; c++) {
            float4 vv = *(const float4*)(Vs + c * 64 + tx * 4);
#pragma unroll
            for (int i = 0; i < 4; i++) {
                float p = Ps[(ty * 4 + i) * 64 + c];
                acc[i][0] = fmaf(p, vv.x, acc[i][0]);
                acc[i][1] = fmaf(p, vv.y, acc[i][1]);
                acc[i][2] = fmaf(p, vv.z, acc[i][2]);
                acc[i][3] = fmaf(p, vv.w, acc[i][3]);
            }
        }
        __syncthreads();
    }

    /* epilogue: normalize, write to [B*S, D] with head interleave */
    const int b = bh >> 4, h = bh & 15;
#pragma unroll
    for (int i = 0; i < 4; i++) {
        float inv = 1.f / l_i[i];
        int srow = q0 + ty * 4 + i;
        float4 o = make_float4(acc[i][0]*inv, acc[i][1]*inv, acc[i][2]*inv, acc[i][3]*inv);
        *(float4*)(AO + (size_t)(b * SEQ + srow) * DIM + h * HD + tx * 4) = o;
    }
}

/* ---------------- launch -------------------------------------------------- */
extern "C" void kernel_launch(void* const* d_in, const int* in_sizes, int n_in,
                              void* d_out, int out_size)
{
    const float* q  = (const float*)d_in[0];
    const float* k  = (const float*)d_in[1];
    const float* v  = (const float*)d_in[2];
    const float* wq = (const float*)d_in[3];
    const float* wk = (const float*)d_in[4];
    const float* wv = (const float*)d_in[5];
    const float* wo = (const float*)d_in[6];

    float *qh, *kh, *vh, *ao;
    cudaGetSymbolAddress((void**)&qh, g_qh);
    cudaGetSymbolAddress((void**)&kh, g_kh);
    cudaGetSymbolAddress((void**)&vh, g_vh);
    cudaGetSymbolAddress((void**)&ao, g_ao);

    cudaFuncSetAttribute(flash_attn, cudaFuncAttributeMaxDynamicSharedMemorySize, 65536);

    dim3 gqkv(DIM / BN, MROWS / BM, 3);      /* 8 x 32 x 3 */
    gemm_qkv<<<gqkv, 256>>>(q, k, v, wq, wk, wv, qh, kh, vh);

    flash_attn<<<dim3(SEQ / 64, BATCH * NH), 256, 65536>>>(qh, kh, vh, ao);

    dim3 gout(DIM / BN, MROWS / BM);         /* 8 x 32 */
    gemm_out<<<gout, 256>>>(ao, wo, (float*)d_out);
}

// round 3
// speedup vs baseline: 1.6760x; 1.6760x over previous
#include <cuda_runtime.h>
#include <cstdint>

#define DIM   1024
#define SEQ   2048
#define BATCH 2
#define NH    16
#define HD    64
#define MROWS (BATCH*SEQ)   /* 4096 */

/* ---------------- scratch (device globals: allocation-free) -------------- */
__device__ float g_qh[BATCH*NH*SEQ*HD];   /* [B,H,S,hd] */
__device__ float g_kh[BATCH*NH*SEQ*HD];
__device__ float g_vh[BATCH*NH*SEQ*HD];
__device__ float g_ao[MROWS*DIM];         /* [B*S, D] attention output */

/* =================== tf32 mma.sync GEMM: C = A @ W^T ===================== */
#define BM 128
#define BN 128
#define BK 32
#define NKT (DIM / BK)          /* 32 k-tiles */
#define TILE_U32 (BM * BK)      /* 4096 u32 per operand tile */

__device__ __forceinline__ uint32_t f32_tf32(float f) {
    uint32_t r;
    asm("cvt.rna.tf32.f32 %0, %1;" : "=r"(r) : "f"(f));
    return r;
}

/* CUTLASS-style xor swizzle: conflict-free STS.128 + fragment LDS.32 */
__device__ __forceinline__ int swz(int row, int k) {
    return row * BK + (k ^ ((row & 7) << 2));
}

__device__ __forceinline__ void mma_tf32(float* d, const uint32_t* a, const uint32_t* b) {
    asm volatile(
        "mma.sync.aligned.m16n8k8.row.col.f32.tf32.tf32.f32 "
        "{%0,%1,%2,%3}, {%4,%5,%6,%7}, {%8,%9}, {%0,%1,%2,%3};\n"
        : "+f"(d[0]), "+f"(d[1]), "+f"(d[2]), "+f"(d[3])
        : "r"(a[0]), "r"(a[1]), "r"(a[2]), "r"(a[3]), "r"(b[0]), "r"(b[1]));
}

__device__ __forceinline__ void stage_tile(
    uint32_t* __restrict__ Asb, uint32_t* __restrict__ Bsb,
    const float* __restrict__ A, const float* __restrict__ W,
    int m0, int n0, int kc, int tid)
{
#pragma unroll
    for (int i = 0; i < 8; i++) {
        int f   = tid + (i << 7);
        int row = f >> 3;
        int c4  = (f & 7) << 2;
        int d   = row * BK + (c4 ^ ((row & 7) << 2));
        float4 av = *(const float4*)(A + (size_t)(m0 + row) * DIM + kc + c4);
        uint4 at = make_uint4(f32_tf32(av.x), f32_tf32(av.y),
                              f32_tf32(av.z), f32_tf32(av.w));
        *(uint4*)(Asb + d) = at;
        float4 bv = *(const float4*)(W + (size_t)(n0 + row) * DIM + kc + c4);
        uint4 bt = make_uint4(f32_tf32(bv.x), f32_tf32(bv.y),
                              f32_tf32(bv.z), f32_tf32(bv.w));
        *(uint4*)(Bsb + d) = bt;
    }
}

__device__ __forceinline__ void gemm_body(
    const float* __restrict__ A, const float* __restrict__ W,
    float* __restrict__ C, int headSplit)
{
    extern __shared__ uint32_t smg[];
    uint32_t* As[2] = { smg,                smg + 2 * TILE_U32 };
    uint32_t* Bs[2] = { smg + TILE_U32,     smg + 3 * TILE_U32 };

    const int tid  = threadIdx.x;
    const int lane = tid & 31;
    const int wid  = tid >> 5;
    const int wm0  = (wid >> 1) << 6;   /* warp m offset: 0 or 64  */
    const int wn0  = (wid & 1) << 6;    /* warp n offset: 0 or 64  */
    const int m0   = blockIdx.y * BM;
    const int n0   = blockIdx.x * BN;
    const int r0   = lane >> 2;         /* groupID 0..7 */
    const int tig  = lane & 3;          /* thread in group */

    float acc[4][8][4];
#pragma unroll
    for (int mt = 0; mt < 4; mt++)
#pragma unroll
        for (int nt = 0; nt < 8; nt++)
#pragma unroll
            for (int e = 0; e < 4; e++) acc[mt][nt][e] = 0.f;

    stage_tile(As[0], Bs[0], A, W, m0, n0, 0, tid);
    __syncthreads();

    for (int kt = 0; kt < NKT; kt++) {
        const int s = kt & 1;
        if (kt + 1 < NKT)
            stage_tile(As[s ^ 1], Bs[s ^ 1], A, W, m0, n0, (kt + 1) * BK, tid);

        const uint32_t* __restrict__ Ab = As[s];
        const uint32_t* __restrict__ Bb = Bs[s];
#pragma unroll
        for (int ks = 0; ks < 4; ks++) {
            const int k = (ks << 3) + tig;
            uint32_t af[4][4], bf[8][2];
#pragma unroll
            for (int mt = 0; mt < 4; mt++) {
                int row = wm0 + (mt << 4) + r0;
                af[mt][0] = Ab[swz(row,     k)];
                af[mt][1] = Ab[swz(row + 8, k)];
                af[mt][2] = Ab[swz(row,     k + 4)];
                af[mt][3] = Ab[swz(row + 8, k + 4)];
            }
#pragma unroll
            for (int nt = 0; nt < 8; nt++) {
                int n = wn0 + (nt << 3) + r0;
                bf[nt][0] = Bb[swz(n, k)];
                bf[nt][1] = Bb[swz(n, k + 4)];
            }
#pragma unroll
            for (int mt = 0; mt < 4; mt++)
#pragma unroll
                for (int nt = 0; nt < 8; nt++)
                    mma_tf32(acc[mt][nt], af[mt], bf[nt]);
        }
        __syncthreads();
    }

    /* epilogue: c0/c1 = (row, 2*tig, +1); c2/c3 = (row+8, ...) */
#pragma unroll
    for (int mt = 0; mt < 4; mt++) {
#pragma unroll
        for (int half = 0; half < 2; half++) {
            const int m = m0 + wm0 + (mt << 4) + r0 + (half << 3);
            if (headSplit) {
                const int b = m >> 11, srow = m & (SEQ - 1);
#pragma unroll
                for (int nt = 0; nt < 8; nt++) {
                    int col = n0 + wn0 + (nt << 3) + (tig << 1);
                    int h = col >> 6, dd = col & 63;
                    float2 val = make_float2(acc[mt][nt][half * 2],
                                             acc[mt][nt][half * 2 + 1]);
                    *(float2*)(C + ((size_t)((b * NH + h) * SEQ + srow) << 6) + dd) = val;
                }
            } else {
#pragma unroll
                for (int nt = 0; nt < 8; nt++) {
                    int col = n0 + wn0 + (nt << 3) + (tig << 1);
                    float2 val = make_float2(acc[mt][nt][half * 2],
                                             acc[mt][nt][half * 2 + 1]);
                    *(float2*)(C + (size_t)m * DIM + col) = val;
                }
            }
        }
    }
}

__global__ __launch_bounds__(128) void gemm_qkv(
    const float* __restrict__ q, const float* __restrict__ k,
    const float* __restrict__ v, const float* __restrict__ wq,
    const float* __restrict__ wk, const float* __restrict__ wv,
    float* __restrict__ qh, float* __restrict__ kh, float* __restrict__ vh)
{
    const float* A; const float* W; float* C;
    if (blockIdx.z == 0)      { A = q; W = wq; C = qh; }
    else if (blockIdx.z == 1) { A = k; W = wk; C = kh; }
    else                      { A = v; W = wv; C = vh; }
    gemm_body(A, W, C, 1);
}

__global__ __launch_bounds__(128) void gemm_out(
    const float* __restrict__ A, const float* __restrict__ W, float* __restrict__ C)
{
    gemm_body(A, W, C, 0);
}

/* ---------------- flash attention (causal), 64x64 tiles, fp32 ------------ */
__global__ __launch_bounds__(256) void flash_attn(
    const float* __restrict__ Qh, const float* __restrict__ Kh,
    const float* __restrict__ Vh, float* __restrict__ AO)
{
    extern __shared__ float sm[];
    float* Qs = sm;            /* [64][64] rows scaled by 1/8  */
    float* Kt = sm + 4096;     /* [k][c] transposed key tile   */
    float* Vs = sm + 8192;     /* [c][d]                       */
    float* Ps = sm + 12288;    /* [r][c] probabilities         */

    const int bh = blockIdx.y;
    const int qt = blockIdx.x;
    const int q0 = qt * 64;
    const float* Qb = Qh + (size_t)bh * SEQ * HD;
    const float* Kb = Kh + (size_t)bh * SEQ * HD;
    const float* Vb = Vh + (size_t)bh * SEQ * HD;

    const int tid = threadIdx.x;
    const int ty = tid >> 4, tx = tid & 15;

    for (int i4 = tid; i4 < 1024; i4 += 256) {
        int r = i4 >> 4, c4 = (i4 & 15) << 2;
        float4 v = *(const float4*)(Qb + (size_t)(q0 + r) * HD + c4);
        v.x *= 0.125f; v.y *= 0.125f; v.z *= 0.125f; v.w *= 0.125f;
        *(float4*)(Qs + r * 64 + c4) = v;
    }

    float m_i[4], l_i[4], acc[4][4];
#pragma unroll
    for (int i = 0; i < 4; i++) {
        m_i[i] = -1e30f; l_i[i] = 0.f;
#pragma unroll
        for (int j = 0; j < 4; j++) acc[i][j] = 0.f;
    }
    __syncthreads();

    for (int kt = 0; kt <= qt; kt++) {
        const int k0 = kt * 64;
        for (int i4 = tid; i4 < 1024; i4 += 256) {
            int r = i4 & 63, c4 = (i4 >> 6) << 2;
            float4 kv = *(const float4*)(Kb + (size_t)(k0 + r) * HD + c4);
            Kt[(c4 + 0) * 64 + r] = kv.x;
            Kt[(c4 + 1) * 64 + r] = kv.y;
            Kt[(c4 + 2) * 64 + r] = kv.z;
            Kt[(c4 + 3) * 64 + r] = kv.w;
        }
        for (int i4 = tid; i4 < 1024; i4 += 256) {
            int r = i4 >> 4, c4 = (i4 & 15) << 2;
            *(float4*)(Vs + r * 64 + c4) =
                *(const float4*)(Vb + (size_t)(k0 + r) * HD + c4);
        }
        __syncthreads();

        float s[4][4];
#pragma unroll
        for (int i = 0; i < 4; i++)
#pragma unroll
            for (int j = 0; j < 4; j++) s[i][j] = 0.f;

#pragma unroll 8
        for (int k = 0; k < 64; k++) {
            float4 kk = *(const float4*)(Kt + k * 64 + tx * 4);
#pragma unroll
            for (int i = 0; i < 4; i++) {
                float qv = Qs[(ty * 4 + i) * 64 + k];
                s[i][0] = fmaf(qv, kk.x, s[i][0]);
                s[i][1] = fmaf(qv, kk.y, s[i][1]);
                s[i][2] = fmaf(qv, kk.z, s[i][2]);
                s[i][3] = fmaf(qv, kk.w, s[i][3]);
            }
        }

        if (kt == qt) {
#pragma unroll
            for (int i = 0; i < 4; i++)
#pragma unroll
                for (int j = 0; j < 4; j++)
                    if (tx * 4 + j > ty * 4 + i) s[i][j] = -1e30f;
        }

#pragma unroll
        for (int i = 0; i < 4; i++) {
            float mx = fmaxf(fmaxf(s[i][0], s[i][1]), fmaxf(s[i][2], s[i][3]));
#pragma unroll
            for (int off = 8; off; off >>= 1)
                mx = fmaxf(mx, __shfl_xor_sync(0xffffffffu, mx, off));
            float mnew = fmaxf(m_i[i], mx);
            float corr = __expf(m_i[i] - mnew);
            float sum = 0.f;
#pragma unroll
            for (int j = 0; j < 4; j++) {
                float p = __expf(s[i][j] - mnew);
                s[i][j] = p; sum += p;
            }
#pragma unroll
            for (int off = 8; off; off >>= 1)
                sum += __shfl_xor_sync(0xffffffffu, sum, off);
            l_i[i] = l_i[i] * corr + sum;
            m_i[i] = mnew;
#pragma unroll
            for (int j = 0; j < 4; j++) acc[i][j] *= corr;
            *(float4*)(Ps + (ty * 4 + i) * 64 + tx * 4) =
                make_float4(s[i][0], s[i][1], s[i][2], s[i][3]);
        }
        __syncthreads();

#pragma unroll 8
        for (int c = 0; c < 64; c++) {
            float4 vv = *(const float4*)(Vs + c * 64 + tx * 4);
#pragma unroll
            for (int i = 0; i < 4; i++) {
                float p = Ps[(ty * 4 + i) * 64 + c];
                acc[i][0] = fmaf(p, vv.x, acc[i][0]);
                acc[i][1] = fmaf(p, vv.y, acc[i][1]);
                acc[i][2] = fmaf(p, vv.z, acc[i][2]);
                acc[i][3] = fmaf(p, vv.w, acc[i][3]);
            }
        }
        __syncthreads();
    }

    const int b = bh >> 4, h = bh & 15;
#pragma unroll
    for (int i = 0; i < 4; i++) {
        float inv = 1.f / l_i[i];
        int srow = q0 + ty * 4 + i;
        float4 o = make_float4(acc[i][0]*inv, acc[i][1]*inv, acc[i][2]*inv, acc[i][3]*inv);
        *(float4*)(AO + (size_t)(b * SEQ + srow) * DIM + h * HD + tx * 4) = o;
    }
}

/* ---------------- launch -------------------------------------------------- */
extern "C" void kernel_launch(void* const* d_in, const int* in_sizes, int n_in,
                              void* d_out, int out_size)
{
    const float* q  = (const float*)d_in[0];
    const float* k  = (const float*)d_in[1];
    const float* v  = (const float*)d_in[2];
    const float* wq = (const float*)d_in[3];
    const float* wk = (const float*)d_in[4];
    const float* wv = (const float*)d_in[5];
    const float* wo = (const float*)d_in[6];

    float *qh, *kh, *vh, *ao;
    cudaGetSymbolAddress((void**)&qh, g_qh);
    cudaGetSymbolAddress((void**)&kh, g_kh);
    cudaGetSymbolAddress((void**)&vh, g_vh);
    cudaGetSymbolAddress((void**)&ao, g_ao);

    const int gemm_smem = 4 * TILE_U32 * 4;   /* 65536 */
    cudaFuncSetAttribute(gemm_qkv, cudaFuncAttributeMaxDynamicSharedMemorySize, gemm_smem);
    cudaFuncSetAttribute(gemm_out, cudaFuncAttributeMaxDynamicSharedMemorySize, gemm_smem);
    cudaFuncSetAttribute(flash_attn, cudaFuncAttributeMaxDynamicSharedMemorySize, 65536);

    dim3 gqkv(DIM / BN, MROWS / BM, 3);        /* 8 x 32 x 3 */
    gemm_qkv<<<gqkv, 128, gemm_smem>>>(q, k, v, wq, wk, wv, qh, kh, vh);

    flash_attn<<<dim3(SEQ / 64, BATCH * NH), 256, 65536>>>(qh, kh, vh, ao);

    dim3 gout(DIM / BN, MROWS / BM);           /* 8 x 32 */
    gemm_out<<<gout, 128, gemm_smem>>>(ao, wo, (float*)d_out);
}

// round 4
// speedup vs baseline: 2.2240x; 1.3269x over previous
#include <cuda_runtime.h>
#include <cstdint>

#define DIM   1024
#define SEQ   2048
#define BATCH 2
#define NH    16
#define HD    64
#define MROWS (BATCH*SEQ)   /* 4096 */

/* ---------------- scratch (device globals: allocation-free) -------------- */
__device__ float g_qh[BATCH*NH*SEQ*HD];   /* [B,H,S,hd] */
__device__ float g_kh[BATCH*NH*SEQ*HD];
__device__ float g_vh[BATCH*NH*SEQ*HD];
__device__ float g_ao[MROWS*DIM];         /* [B*S, D] attention output */

__device__ __forceinline__ uint32_t f32_tf32(float f) {
    uint32_t r;
    asm("cvt.rna.tf32.f32 %0, %1;" : "=r"(r) : "f"(f));
    return r;
}

__device__ __forceinline__ void mma_tf32(float* d, const uint32_t* a, const uint32_t* b) {
    asm volatile(
        "mma.sync.aligned.m16n8k8.row.col.f32.tf32.tf32.f32 "
        "{%0,%1,%2,%3}, {%4,%5,%6,%7}, {%8,%9}, {%0,%1,%2,%3};\n"
        : "+f"(d[0]), "+f"(d[1]), "+f"(d[2]), "+f"(d[3])
        : "r"(a[0]), "r"(a[1]), "r"(a[2]), "r"(a[3]), "r"(b[0]), "r"(b[1]));
}

/* =================== tf32 GEMM: C = A @ W^T, 256 thr, 8 warps ============ */
#define BM 128
#define BN 128
#define BK 32
#define NKT (DIM / BK)
#define TILE_U32 (BM * BK)

/* xor swizzle for 32-wide rows: conflict-free STS.128 + LDS.32 */
__device__ __forceinline__ int swz(int row, int k) {
    return row * BK + (k ^ ((row & 7) << 2));
}

__device__ __forceinline__ void stage_tile(
    uint32_t* __restrict__ Asb, uint32_t* __restrict__ Bsb,
    const float* __restrict__ A, const float* __restrict__ W,
    int m0, int n0, int kc, int tid)
{
#pragma unroll
    for (int i = 0; i < 4; i++) {
        int f   = tid + (i << 8);
        int row = f >> 3;
        int c4  = (f & 7) << 2;
        int d   = row * BK + (c4 ^ ((row & 7) << 2));
        float4 av = *(const float4*)(A + (size_t)(m0 + row) * DIM + kc + c4);
        *(uint4*)(Asb + d) = make_uint4(f32_tf32(av.x), f32_tf32(av.y),
                                        f32_tf32(av.z), f32_tf32(av.w));
        float4 bv = *(const float4*)(W + (size_t)(n0 + row) * DIM + kc + c4);
        *(uint4*)(Bsb + d) = make_uint4(f32_tf32(bv.x), f32_tf32(bv.y),
                                        f32_tf32(bv.z), f32_tf32(bv.w));
    }
}

__device__ __forceinline__ void gemm_body(
    const float* __restrict__ A, const float* __restrict__ W,
    float* __restrict__ C, int headSplit)
{
    extern __shared__ uint32_t smg[];
    uint32_t* As[2] = { smg,            smg + 2 * TILE_U32 };
    uint32_t* Bs[2] = { smg + TILE_U32, smg + 3 * TILE_U32 };

    const int tid  = threadIdx.x;
    const int lane = tid & 31;
    const int wid  = tid >> 5;
    const int wm0  = (wid >> 2) << 6;   /* 0 or 64 */
    const int wn0  = (wid & 3) << 5;    /* 0,32,64,96 */
    const int m0   = blockIdx.y * BM;
    const int n0   = blockIdx.x * BN;
    const int r0   = lane >> 2;
    const int tig  = lane & 3;

    float acc[4][4][4];
#pragma unroll
    for (int mt = 0; mt < 4; mt++)
#pragma unroll
        for (int nt = 0; nt < 4; nt++)
#pragma unroll
            for (int e = 0; e < 4; e++) acc[mt][nt][e] = 0.f;

    stage_tile(As[0], Bs[0], A, W, m0, n0, 0, tid);
    __syncthreads();

    for (int kt = 0; kt < NKT; kt++) {
        const int s = kt & 1;
        if (kt + 1 < NKT)
            stage_tile(As[s ^ 1], Bs[s ^ 1], A, W, m0, n0, (kt + 1) * BK, tid);

        const uint32_t* __restrict__ Ab = As[s];
        const uint32_t* __restrict__ Bb = Bs[s];
#pragma unroll
        for (int ks = 0; ks < 4; ks++) {
            const int k = (ks << 3) + tig;
            uint32_t af[4][4], bf[4][2];
#pragma unroll
            for (int mt = 0; mt < 4; mt++) {
                int row = wm0 + (mt << 4) + r0;
                af[mt][0] = Ab[swz(row,     k)];
                af[mt][1] = Ab[swz(row + 8, k)];
                af[mt][2] = Ab[swz(row,     k + 4)];
                af[mt][3] = Ab[swz(row + 8, k + 4)];
            }
#pragma unroll
            for (int nt = 0; nt < 4; nt++) {
                int n = wn0 + (nt << 3) + r0;
                bf[nt][0] = Bb[swz(n, k)];
                bf[nt][1] = Bb[swz(n, k + 4)];
            }
#pragma unroll
            for (int mt = 0; mt < 4; mt++)
#pragma unroll
                for (int nt = 0; nt < 4; nt++)
                    mma_tf32(acc[mt][nt], af[mt], bf[nt]);
        }
        __syncthreads();
    }

#pragma unroll
    for (int mt = 0; mt < 4; mt++) {
#pragma unroll
        for (int half = 0; half < 2; half++) {
            const int m = m0 + wm0 + (mt << 4) + r0 + (half << 3);
            if (headSplit) {
                const int b = m >> 11, srow = m & (SEQ - 1);
#pragma unroll
                for (int nt = 0; nt < 4; nt++) {
                    int col = n0 + wn0 + (nt << 3) + (tig << 1);
                    int h = col >> 6, dd = col & 63;
                    float2 val = make_float2(acc[mt][nt][half * 2],
                                             acc[mt][nt][half * 2 + 1]);
                    *(float2*)(C + ((size_t)((b * NH + h) * SEQ + srow) << 6) + dd) = val;
                }
            } else {
#pragma unroll
                for (int nt = 0; nt < 4; nt++) {
                    int col = n0 + wn0 + (nt << 3) + (tig << 1);
                    float2 val = make_float2(acc[mt][nt][half * 2],
                                             acc[mt][nt][half * 2 + 1]);
                    *(float2*)(C + (size_t)m * DIM + col) = val;
                }
            }
        }
    }
}

__global__ __launch_bounds__(256) void gemm_qkv(
    const float* __restrict__ q, const float* __restrict__ k,
    const float* __restrict__ v, const float* __restrict__ wq,
    const float* __restrict__ wk, const float* __restrict__ wv,
    float* __restrict__ qh, float* __restrict__ kh, float* __restrict__ vh)
{
    const float* A; const float* W; float* C;
    if (blockIdx.z == 0)      { A = q; W = wq; C = qh; }
    else if (blockIdx.z == 1) { A = k; W = wk; C = kh; }
    else                      { A = v; W = wv; C = vh; }
    gemm_body(A, W, C, 1);
}

__global__ __launch_bounds__(256) void gemm_out(
    const float* __restrict__ A, const float* __restrict__ W, float* __restrict__ C)
{
    gemm_body(A, W, C, 0);
}

/* ============ tensor-core flash attention (causal), tf32 mma ============== */
/* block: 128 thr / 4 warps; Q tile 128 rows (32/warp); K/V tiles 64 keys    */
#define SW64(row, k) ((row) * 64 + ((k) ^ (((row) & 7) << 3)))

__global__ __launch_bounds__(128) void flash_attn(
    const float* __restrict__ Qh, const float* __restrict__ Kh,
    const float* __restrict__ Vh, float* __restrict__ AO)
{
    extern __shared__ uint32_t fsm[];
    uint32_t* Qs = fsm;                  /* 128x64 tf32, swizzled */
    uint32_t* Ks = fsm + 8192;           /* 64x64  [key][hd]      */
    uint32_t* Vt = fsm + 12288;          /* 64x64  [hd][key]      */
    uint32_t* Ps = fsm + 16384;          /* 128x64 P (per-warp)   */

    const int bh = blockIdx.y;
    const int qt = blockIdx.x;
    const int q0 = qt * 128;
    const float* Qb = Qh + (size_t)bh * SEQ * HD;
    const float* Kb = Kh + (size_t)bh * SEQ * HD;
    const float* Vb = Vh + (size_t)bh * SEQ * HD;

    const int tid  = threadIdx.x;
    const int lane = tid & 31;
    const int wid  = tid >> 5;
    const int r0   = lane >> 2;
    const int tig  = lane & 3;
    const int wq   = wid << 5;           /* warp's q-row offset   */

    /* load Q tile (pre-scaled by 1/sqrt(hd), tf32) */
#pragma unroll
    for (int i = 0; i < 16; i++) {
        int f = tid + (i << 7);
        int row = f >> 4, c4 = (f & 15) << 2;
        float4 v = *(const float4*)(Qb + (size_t)(q0 + row) * HD + c4);
        *(uint4*)(Qs + SW64(row, c4)) = make_uint4(
            f32_tf32(v.x * 0.125f), f32_tf32(v.y * 0.125f),
            f32_tf32(v.z * 0.125f), f32_tf32(v.w * 0.125f));
    }

    float o[2][8][4];
    float mi[4], li[4];
#pragma unroll
    for (int i = 0; i < 4; i++) { mi[i] = -1e30f; li[i] = 0.f; }
#pragma unroll
    for (int mt = 0; mt < 2; mt++)
#pragma unroll
        for (int nt = 0; nt < 8; nt++)
#pragma unroll
            for (int e = 0; e < 4; e++) o[mt][nt][e] = 0.f;

    const int nkt = 2 * qt + 2;
    for (int kt = 0; kt < nkt; kt++) {
        const int k0 = kt << 6;
        /* K tile: [key][hd] rows, coalesced LDG.128, swizzled STS.128 */
        const float* Kp = Kb + (size_t)k0 * HD;
#pragma unroll
        for (int i = 0; i < 8; i++) {
            int f = tid + (i << 7);
            int row = f >> 4, c4 = (f & 15) << 2;
            float4 kv = *(const float4*)(Kp + (size_t)row * HD + c4);
            *(uint4*)(Ks + SW64(row, c4)) = make_uint4(
                f32_tf32(kv.x), f32_tf32(kv.y), f32_tf32(kv.z), f32_tf32(kv.w));
        }
        /* V tile transposed: key-per-lane, conflict-free scattered STS.32 */
        const float* Vp = Vb + (size_t)k0 * HD;
#pragma unroll
        for (int i = 0; i < 8; i++) {
            int f = tid + (i << 7);
            int key = f & 63, c4 = (f >> 6) << 2;
            float4 vv = *(const float4*)(Vp + (size_t)key * HD + c4);
            Vt[SW64(c4 + 0, key)] = f32_tf32(vv.x);
            Vt[SW64(c4 + 1, key)] = f32_tf32(vv.y);
            Vt[SW64(c4 + 2, key)] = f32_tf32(vv.z);
            Vt[SW64(c4 + 3, key)] = f32_tf32(vv.w);
        }
        __syncthreads();

        const bool active = (k0 <= q0 + wq + 31);
        if (active) {
            /* S = Q K^T for this warp's 32 rows x 64 keys */
            float s[2][8][4];
#pragma unroll
            for (int mt = 0; mt < 2; mt++)
#pragma unroll
                for (int nt = 0; nt < 8; nt++)
#pragma unroll
                    for (int e = 0; e < 4; e++) s[mt][nt][e] = 0.f;

#pragma unroll
            for (int ks = 0; ks < 8; ks++) {
                const int k = (ks << 3) + tig;
                uint32_t af[2][4], bf[8][2];
#pragma unroll
                for (int mt = 0; mt < 2; mt++) {
                    int row = wq + (mt << 4) + r0;
                    af[mt][0] = Qs[SW64(row,     k)];
                    af[mt][1] = Qs[SW64(row + 8, k)];
                    af[mt][2] = Qs[SW64(row,     k + 4)];
                    af[mt][3] = Qs[SW64(row + 8, k + 4)];
                }
#pragma unroll
                for (int nt = 0; nt < 8; nt++) {
                    int n = (nt << 3) + r0;
                    bf[nt][0] = Ks[SW64(n, k)];
                    bf[nt][1] = Ks[SW64(n, k + 4)];
                }
#pragma unroll
                for (int mt = 0; mt < 2; mt++)
#pragma unroll
                    for (int nt = 0; nt < 8; nt++)
                        mma_tf32(s[mt][nt], af[mt], bf[nt]);
            }

            /* causal mask (only near the diagonal) */
            if (k0 + 63 > q0 + wq) {
#pragma unroll
                for (int mt = 0; mt < 2; mt++)
#pragma unroll
                    for (int nt = 0; nt < 8; nt++)
#pragma unroll
                        for (int e = 0; e < 4; e++) {
                            int rg = q0 + wq + (mt << 4) + ((e >> 1) << 3) + r0;
                            int cg = k0 + (nt << 3) + (tig << 1) + (e & 1);
                            if (cg > rg) s[mt][nt][e] = -1e30f;
                        }
            }

            /* online softmax; rows indexed by (mt, half) */
#pragma unroll
            for (int mt = 0; mt < 2; mt++) {
#pragma unroll
                for (int half = 0; half < 2; half++) {
                    const int ri = mt * 2 + half;
                    float mx = -1e30f;
#pragma unroll
                    for (int nt = 0; nt < 8; nt++)
                        mx = fmaxf(mx, fmaxf(s[mt][nt][half*2], s[mt][nt][half*2+1]));
                    mx = fmaxf(mx, __shfl_xor_sync(0xffffffffu, mx, 1));
                    mx = fmaxf(mx, __shfl_xor_sync(0xffffffffu, mx, 2));
                    float mnew = fmaxf(mi[ri], mx);
                    float corr = __expf(mi[ri] - mnew);
                    float sum = 0.f;
                    const int prow = wq + (mt << 4) + (half << 3) + r0;
#pragma unroll
                    for (int nt = 0; nt < 8; nt++) {
                        float p0 = __expf(s[mt][nt][half*2]     - mnew);
                        float p1 = __expf(s[mt][nt][half*2 + 1] - mnew);
                        sum += p0 + p1;
                        uint2 pp = make_uint2(f32_tf32(p0), f32_tf32(p1));
                        *(uint2*)(Ps + SW64(prow, (nt << 3) + (tig << 1))) = pp;
                    }
                    sum += __shfl_xor_sync(0xffffffffu, sum, 1);
                    sum += __shfl_xor_sync(0xffffffffu, sum, 2);
                    li[ri] = li[ri] * corr + sum;
                    mi[ri] = mnew;
#pragma unroll
                    for (int nt = 0; nt < 8; nt++) {
                        o[mt][nt][half*2]     *= corr;
                        o[mt][nt][half*2 + 1] *= corr;
                    }
                }
            }
            __syncwarp();

            /* O += P V  (A = Ps rows of this warp, B = Vt) */
#pragma unroll
            for (int ks = 0; ks < 8; ks++) {
                const int k = (ks << 3) + tig;
                uint32_t af[2][4], bf[8][2];
#pragma unroll
                for (int mt = 0; mt < 2; mt++) {
                    int row = wq + (mt << 4) + r0;
                    af[mt][0] = Ps[SW64(row,     k)];
                    af[mt][1] = Ps[SW64(row + 8, k)];
                    af[mt][2] = Ps[SW64(row,     k + 4)];
                    af[mt][3] = Ps[SW64(row + 8, k + 4)];
                }
#pragma unroll
                for (int nt = 0; nt < 8; nt++) {
                    int n = (nt << 3) + r0;
                    bf[nt][0] = Vt[SW64(n, k)];
                    bf[nt][1] = Vt[SW64(n, k + 4)];
                }
#pragma unroll
                for (int mt = 0; mt < 2; mt++)
#pragma unroll
                    for (int nt = 0; nt < 8; nt++)
                        mma_tf32(o[mt][nt], af[mt], bf[nt]);
            }
        }
        __syncthreads();
    }

    /* epilogue: normalize, write [B*S, D] head-interleaved */
    const int b = bh >> 4, h = bh & 15;
#pragma unroll
    for (int mt = 0; mt < 2; mt++) {
#pragma unroll
        for (int half = 0; half < 2; half++) {
            const float inv = 1.f / li[mt * 2 + half];
            const int rg = q0 + wq + (mt << 4) + (half << 3) + r0;
            float* row = AO + (size_t)(b * SEQ + rg) * DIM + (h << 6);
#pragma unroll
            for (int nt = 0; nt < 8; nt++) {
                float2 val = make_float2(o[mt][nt][half*2] * inv,
                                         o[mt][nt][half*2 + 1] * inv);
                *(float2*)(row + (nt << 3) + (tig << 1)) = val;
            }
        }
    }
}

/* ---------------- launch -------------------------------------------------- */
extern "C" void kernel_launch(void* const* d_in, const int* in_sizes, int n_in,
                              void* d_out, int out_size)
{
    const float* q  = (const float*)d_in[0];
    const float* k  = (const float*)d_in[1];
    const float* v  = (const float*)d_in[2];
    const float* wq = (const float*)d_in[3];
    const float* wk = (const float*)d_in[4];
    const float* wv = (const float*)d_in[5];
    const float* wo = (const float*)d_in[6];

    float *qh, *kh, *vh, *ao;
    cudaGetSymbolAddress((void**)&qh, g_qh);
    cudaGetSymbolAddress((void**)&kh, g_kh);
    cudaGetSymbolAddress((void**)&vh, g_vh);
    cudaGetSymbolAddress((void**)&ao, g_ao);

    const int gemm_smem  = 4 * TILE_U32 * 4;   /* 65536 */
    const int flash_smem = (8192 + 4096 + 4096 + 8192) * 4;  /* 98304 */
    cudaFuncSetAttribute(gemm_qkv,  cudaFuncAttributeMaxDynamicSharedMemorySize, gemm_smem);
    cudaFuncSetAttribute(gemm_out,  cudaFuncAttributeMaxDynamicSharedMemorySize, gemm_smem);
    cudaFuncSetAttribute(flash_attn, cudaFuncAttributeMaxDynamicSharedMemorySize, flash_smem);

    dim3 gqkv(DIM / BN, MROWS / BM, 3);        /* 8 x 32 x 3 */
    gemm_qkv<<<gqkv, 256, gemm_smem>>>(q, k, v, wq, wk, wv, qh, kh, vh);

    flash_attn<<<dim3(SEQ / 128, BATCH * NH), 128, flash_smem>>>(qh, kh, vh, ao);

    dim3 gout(DIM / BN, MROWS / BM);           /* 8 x 32 */
    gemm_out<<<gout, 256, gemm_smem>>>(ao, wo, (float*)d_out);
}

// round 5
// speedup vs baseline: 2.8860x; 1.2977x over previous
#include <cuda_runtime.h>
#include <cstdint>

#define DIM   1024
#define SEQ   2048
#define BATCH 2
#define NH    16
#define HD    64
#define MROWS (BATCH*SEQ)   /* 4096 */

/* ---------------- scratch (device globals: allocation-free) -------------- */
__device__ uint32_t g_qt[MROWS*DIM];      /* tf32 bits of q,k,v inputs */
__device__ uint32_t g_kt[MROWS*DIM];
__device__ uint32_t g_vt[MROWS*DIM];
__device__ uint32_t g_wq[DIM*DIM];        /* tf32 bits of weights */
__device__ uint32_t g_wk[DIM*DIM];
__device__ uint32_t g_wv[DIM*DIM];
__device__ uint32_t g_wo[DIM*DIM];
__device__ uint32_t g_qh[BATCH*NH*SEQ*HD];  /* tf32 [B,H,S,hd], pre-scaled */
__device__ uint32_t g_kh[BATCH*NH*SEQ*HD];
__device__ uint32_t g_vh[BATCH*NH*SEQ*HD];
__device__ uint32_t g_ao[MROWS*DIM];        /* tf32 [B*S, D] attn output */

__device__ __forceinline__ uint32_t f32_tf32(float f) {
    uint32_t r;
    asm("cvt.rna.tf32.f32 %0, %1;" : "=r"(r) : "f"(f));
    return r;
}

__device__ __forceinline__ void mma_tf32(float* d, const uint32_t* a, const uint32_t* b) {
    asm volatile(
        "mma.sync.aligned.m16n8k8.row.col.f32.tf32.tf32.f32 "
        "{%0,%1,%2,%3}, {%4,%5,%6,%7}, {%8,%9}, {%0,%1,%2,%3};\n"
        : "+f"(d[0]), "+f"(d[1]), "+f"(d[2]), "+f"(d[3])
        : "r"(a[0]), "r"(a[1]), "r"(a[2]), "r"(a[3]), "r"(b[0]), "r"(b[1]));
}

__device__ __forceinline__ void cp16(uint32_t* smem_dst, const uint32_t* gsrc) {
    uint32_t sa = (uint32_t)__cvta_generic_to_shared(smem_dst);
    asm volatile("cp.async.cg.shared.global [%0], [%1], 16;"
                 :: "r"(sa), "l"(gsrc) : "memory");
}
#define CP_COMMIT() asm volatile("cp.async.commit_group;" ::: "memory")
#define CP_WAIT(n)  asm volatile("cp.async.wait_group %0;" :: "n"(n) : "memory")

/* ------------------- fp32 -> tf32 bits convert --------------------------- */
__global__ __launch_bounds__(256) void cvt_tf32_kernel(
    const float* __restrict__ src, uint32_t* __restrict__ dst, int n4)
{
    int i = blockIdx.x * 256 + threadIdx.x;
    if (i < n4) {
        float4 v = *(const float4*)(src + i * 4);
        *(uint4*)(dst + i * 4) = make_uint4(f32_tf32(v.x), f32_tf32(v.y),
                                            f32_tf32(v.z), f32_tf32(v.w));
    }
}

/* =================== tf32 GEMM: C = A @ W^T =============================== */
/* block tile 128x256x32, 256 thr / 8 warps, warp tile 64x64, 3-stage async  */
#define BM 128
#define BN 256
#define BK 32
#define NKT (DIM / BK)
#define A_U32 (BM * BK)            /* 4096  */
#define B_U32 (BN * BK)            /* 8192  */
#define STG_U32 (A_U32 + B_U32)    /* 12288 */
#define GEMM_SMEM (3 * STG_U32 * 4)  /* 147456 B */

__device__ __forceinline__ int swz(int row, int k) {
    return row * BK + (k ^ ((row & 7) << 2));
}

__device__ __forceinline__ void stage_async(
    uint32_t* __restrict__ As, uint32_t* __restrict__ Bs,
    const uint32_t* __restrict__ A, const uint32_t* __restrict__ W,
    int m0, int n0, int kc, int tid)
{
#pragma unroll
    for (int i = 0; i < 4; i++) {           /* A: 128 rows */
        int f = tid + (i << 8);
        int row = f >> 3, c4 = (f & 7) << 2;
        cp16(As + swz(row, c4), A + (size_t)(m0 + row) * DIM + kc + c4);
    }
#pragma unroll
    for (int i = 0; i < 8; i++) {           /* B: 256 rows */
        int f = tid + (i << 8);
        int row = f >> 3, c4 = (f & 7) << 2;
        cp16(Bs + swz(row, c4), W + (size_t)(n0 + row) * DIM + kc + c4);
    }
}

/* mode: 0 = fp32 flat output (final), 1 = tf32 head-split (qkv)            */
__device__ __forceinline__ void gemm_body(
    const uint32_t* __restrict__ A, const uint32_t* __restrict__ W,
    float* __restrict__ Cf, uint32_t* __restrict__ Ch, int mode, float scale)
{
    extern __shared__ uint32_t smg[];
    uint32_t* As[3] = { smg, smg + STG_U32, smg + 2 * STG_U32 };
    uint32_t* Bs[3] = { smg + A_U32, smg + STG_U32 + A_U32, smg + 2 * STG_U32 + A_U32 };

    const int tid  = threadIdx.x;
    const int lane = tid & 31;
    const int wid  = tid >> 5;
    const int wm0  = (wid & 1) << 6;        /* 0 or 64          */
    const int wn0  = (wid >> 1) << 6;       /* 0,64,128,192     */
    const int m0   = blockIdx.y * BM;
    const int n0   = blockIdx.x * BN;
    const int r0   = lane >> 2;
    const int tig  = lane & 3;

    float acc[4][8][4];
#pragma unroll
    for (int mt = 0; mt < 4; mt++)
#pragma unroll
        for (int nt = 0; nt < 8; nt++)
#pragma unroll
            for (int e = 0; e < 4; e++) acc[mt][nt][e] = 0.f;

    stage_async(As[0], Bs[0], A, W, m0, n0, 0, tid);  CP_COMMIT();
    stage_async(As[1], Bs[1], A, W, m0, n0, BK, tid); CP_COMMIT();

    for (int kt = 0; kt < NKT; kt++) {
        const int s = kt % 3;
        if (kt + 2 < NKT)
            stage_async(As[(kt + 2) % 3], Bs[(kt + 2) % 3], A, W,
                        m0, n0, (kt + 2) * BK, tid);
        CP_COMMIT();               /* always commit (possibly empty group) */
        CP_WAIT(2);                /* stage kt resident */
        __syncthreads();

        const uint32_t* __restrict__ Ab = As[s];
        const uint32_t* __restrict__ Bb = Bs[s];
#pragma unroll
        for (int ks = 0; ks < 4; ks++) {
            const int k = (ks << 3) + tig;
            uint32_t af[4][4], bf[8][2];
#pragma unroll
            for (int mt = 0; mt < 4; mt++) {
                int row = wm0 + (mt << 4) + r0;
                af[mt][0] = Ab[swz(row,     k)];
                af[mt][1] = Ab[swz(row + 8, k)];
                af[mt][2] = Ab[swz(row,     k + 4)];
                af[mt][3] = Ab[swz(row + 8, k + 4)];
            }
#pragma unroll
            for (int nt = 0; nt < 8; nt++) {
                int n = wn0 + (nt << 3) + r0;
                bf[nt][0] = Bb[swz(n, k)];
                bf[nt][1] = Bb[swz(n, k + 4)];
            }
#pragma unroll
            for (int mt = 0; mt < 4; mt++)
#pragma unroll
                for (int nt = 0; nt < 8; nt++)
                    mma_tf32(acc[mt][nt], af[mt], bf[nt]);
        }
        __syncthreads();
    }

#pragma unroll
    for (int mt = 0; mt < 4; mt++) {
#pragma unroll
        for (int half = 0; half < 2; half++) {
            const int m = m0 + wm0 + (mt << 4) + r0 + (half << 3);
            if (mode == 1) {
                const int b = m >> 11, srow = m & (SEQ - 1);
#pragma unroll
                for (int nt = 0; nt < 8; nt++) {
                    int col = n0 + wn0 + (nt << 3) + (tig << 1);
                    int h = col >> 6, dd = col & 63;
                    uint2 val = make_uint2(
                        f32_tf32(acc[mt][nt][half * 2]     * scale),
                        f32_tf32(acc[mt][nt][half * 2 + 1] * scale));
                    *(uint2*)(Ch + ((size_t)((b * NH + h) * SEQ + srow) << 6) + dd) = val;
                }
            } else {
#pragma unroll
                for (int nt = 0; nt < 8; nt++) {
                    int col = n0 + wn0 + (nt << 3) + (tig << 1);
                    float2 val = make_float2(acc[mt][nt][half * 2],
                                             acc[mt][nt][half * 2 + 1]);
                    *(float2*)(Cf + (size_t)m * DIM + col) = val;
                }
            }
        }
    }
}

__global__ __launch_bounds__(256) void gemm_qkv(
    const uint32_t* __restrict__ qt, const uint32_t* __restrict__ kt_,
    const uint32_t* __restrict__ vt, const uint32_t* __restrict__ wq,
    const uint32_t* __restrict__ wk, const uint32_t* __restrict__ wv,
    uint32_t* __restrict__ qh, uint32_t* __restrict__ kh, uint32_t* __restrict__ vh)
{
    const uint32_t* A; const uint32_t* W; uint32_t* C; float scale;
    if (blockIdx.z == 0)      { A = qt;  W = wq; C = qh; scale = 0.125f; }
    else if (blockIdx.z == 1) { A = kt_; W = wk; C = kh; scale = 1.0f;   }
    else                      { A = vt;  W = wv; C = vh; scale = 1.0f;   }
    gemm_body(A, W, nullptr, C, 1, scale);
}

__global__ __launch_bounds__(256) void gemm_out(
    const uint32_t* __restrict__ A, const uint32_t* __restrict__ W,
    float* __restrict__ C)
{
    gemm_body(A, W, C, nullptr, 0, 1.0f);
}

/* ============ tensor-core flash attention (causal), tf32 mma ============== */
#define SW64(row, k) ((row) * 64 + ((k) ^ (((row) & 7) << 3)))

__global__ __launch_bounds__(128) void flash_attn(
    const uint32_t* __restrict__ Qh, const uint32_t* __restrict__ Kh,
    const uint32_t* __restrict__ Vh, uint32_t* __restrict__ AO)
{
    extern __shared__ uint32_t fsm[];
    uint32_t* Qs = fsm;                  /* 128x64 tf32, swizzled */
    uint32_t* Ks = fsm + 8192;           /* 64x64  [key][hd]      */
    uint32_t* Vt = fsm + 12288;          /* 64x64  [hd][key]      */
    uint32_t* Ps = fsm + 16384;          /* 128x64 P              */

    const int bh = blockIdx.y;
    const int qt = blockIdx.x;
    const int q0 = qt * 128;
    const uint32_t* Qb = Qh + (size_t)bh * SEQ * HD;
    const uint32_t* Kb = Kh + (size_t)bh * SEQ * HD;
    const uint32_t* Vb = Vh + (size_t)bh * SEQ * HD;

    const int tid  = threadIdx.x;
    const int lane = tid & 31;
    const int wid  = tid >> 5;
    const int r0   = lane >> 2;
    const int tig  = lane & 3;
    const int wq   = wid << 5;

    /* async-load Q tile (already tf32 + pre-scaled) */
#pragma unroll
    for (int i = 0; i < 16; i++) {
        int f = tid + (i << 7);
        int row = f >> 4, c4 = (f & 15) << 2;
        cp16(Qs + SW64(row, c4), Qb + (size_t)(q0 + row) * HD + c4);
    }
    CP_COMMIT();

    float o[2][8][4];
    float mi[4], li[4];
#pragma unroll
    for (int i = 0; i < 4; i++) { mi[i] = -1e30f; li[i] = 0.f; }
#pragma unroll
    for (int mt = 0; mt < 2; mt++)
#pragma unroll
        for (int nt = 0; nt < 8; nt++)
#pragma unroll
            for (int e = 0; e < 4; e++) o[mt][nt][e] = 0.f;

    const int nkt = 2 * qt + 2;
    for (int kt = 0; kt < nkt; kt++) {
        const int k0 = kt << 6;
        const uint32_t* Kp = Kb + (size_t)k0 * HD;
#pragma unroll
        for (int i = 0; i < 8; i++) {
            int f = tid + (i << 7);
            int row = f >> 4, c4 = (f & 15) << 2;
            cp16(Ks + SW64(row, c4), Kp + (size_t)row * HD + c4);
        }
        CP_COMMIT();
        /* V tile transposed: raw bit scatter (conflict-free) */
        const uint32_t* Vp = Vb + (size_t)k0 * HD;
#pragma unroll
        for (int i = 0; i < 8; i++) {
            int f = tid + (i << 7);
            int key = f & 63, c4 = (f >> 6) << 2;
            uint4 vv = *(const uint4*)(Vp + (size_t)key * HD + c4);
            Vt[SW64(c4 + 0, key)] = vv.x;
            Vt[SW64(c4 + 1, key)] = vv.y;
            Vt[SW64(c4 + 2, key)] = vv.z;
            Vt[SW64(c4 + 3, key)] = vv.w;
        }
        CP_WAIT(0);
        __syncthreads();

        const bool active = (k0 <= q0 + wq + 31);
        if (active) {
            float s[2][8][4];
#pragma unroll
            for (int mt = 0; mt < 2; mt++)
#pragma unroll
                for (int nt = 0; nt < 8; nt++)
#pragma unroll
                    for (int e = 0; e < 4; e++) s[mt][nt][e] = 0.f;

#pragma unroll
            for (int ks = 0; ks < 8; ks++) {
                const int k = (ks << 3) + tig;
                uint32_t af[2][4], bf[8][2];
#pragma unroll
                for (int mt = 0; mt < 2; mt++) {
                    int row = wq + (mt << 4) + r0;
                    af[mt][0] = Qs[SW64(row,     k)];
                    af[mt][1] = Qs[SW64(row + 8, k)];
                    af[mt][2] = Qs[SW64(row,     k + 4)];
                    af[mt][3] = Qs[SW64(row + 8, k + 4)];
                }
#pragma unroll
                for (int nt = 0; nt < 8; nt++) {
                    int n = (nt << 3) + r0;
                    bf[nt][0] = Ks[SW64(n, k)];
                    bf[nt][1] = Ks[SW64(n, k + 4)];
                }
#pragma unroll
                for (int mt = 0; mt < 2; mt++)
#pragma unroll
                    for (int nt = 0; nt < 8; nt++)
                        mma_tf32(s[mt][nt], af[mt], bf[nt]);
            }

            if (k0 + 63 > q0 + wq) {
#pragma unroll
                for (int mt = 0; mt < 2; mt++)
#pragma unroll
                    for (int nt = 0; nt < 8; nt++)
#pragma unroll
                        for (int e = 0; e < 4; e++) {
                            int rg = q0 + wq + (mt << 4) + ((e >> 1) << 3) + r0;
                            int cg = k0 + (nt << 3) + (tig << 1) + (e & 1);
                            if (cg > rg) s[mt][nt][e] = -1e30f;
                        }
            }

#pragma unroll
            for (int mt = 0; mt < 2; mt++) {
#pragma unroll
                for (int half = 0; half < 2; half++) {
                    const int ri = mt * 2 + half;
                    float mx = -1e30f;
#pragma unroll
                    for (int nt = 0; nt < 8; nt++)
                        mx = fmaxf(mx, fmaxf(s[mt][nt][half*2], s[mt][nt][half*2+1]));
                    mx = fmaxf(mx, __shfl_xor_sync(0xffffffffu, mx, 1));
                    mx = fmaxf(mx, __shfl_xor_sync(0xffffffffu, mx, 2));
                    float mnew = fmaxf(mi[ri], mx);
                    float corr = __expf(mi[ri] - mnew);
                    float sum = 0.f;
                    const int prow = wq + (mt << 4) + (half << 3) + r0;
#pragma unroll
                    for (int nt = 0; nt < 8; nt++) {
                        float p0 = __expf(s[mt][nt][half*2]     - mnew);
                        float p1 = __expf(s[mt][nt][half*2 + 1] - mnew);
                        sum += p0 + p1;
                        *(uint2*)(Ps + SW64(prow, (nt << 3) + (tig << 1))) =
                            make_uint2(f32_tf32(p0), f32_tf32(p1));
                    }
                    sum += __shfl_xor_sync(0xffffffffu, sum, 1);
                    sum += __shfl_xor_sync(0xffffffffu, sum, 2);
                    li[ri] = li[ri] * corr + sum;
                    mi[ri] = mnew;
#pragma unroll
                    for (int nt = 0; nt < 8; nt++) {
                        o[mt][nt][half*2]     *= corr;
                        o[mt][nt][half*2 + 1] *= corr;
                    }
                }
            }
            __syncwarp();

#pragma unroll
            for (int ks = 0; ks < 8; ks++) {
                const int k = (ks << 3) + tig;
                uint32_t af[2][4], bf[8][2];
#pragma unroll
                for (int mt = 0; mt < 2; mt++) {
                    int row = wq + (mt << 4) + r0;
                    af[mt][0] = Ps[SW64(row,     k)];
                    af[mt][1] = Ps[SW64(row + 8, k)];
                    af[mt][2] = Ps[SW64(row,     k + 4)];
                    af[mt][3] = Ps[SW64(row + 4, k + 4) + (4 << 6) - (4 << 6)];
                }
                /* fix: af[mt][3] must be row+8, k+4 */
                for (int mt = 0; mt < 2; mt++) {
                    int row = wq + (mt << 4) + r0;
                    af[mt][3] = Ps[SW64(row + 8, k + 4)];
                }
#pragma unroll
                for (int nt = 0; nt < 8; nt++) {
                    int n = (nt << 3) + r0;
                    bf[nt][0] = Vt[SW64(n, k)];
                    bf[nt][1] = Vt[SW64(n, k + 4)];
                }
#pragma unroll
                for (int mt = 0; mt < 2; mt++)
#pragma unroll
                    for (int nt = 0; nt < 8; nt++)
                        mma_tf32(o[mt][nt], af[mt], bf[nt]);
            }
        }
        __syncthreads();
    }

    /* epilogue: normalize, store tf32 bits into AO */
    const int b = bh >> 4, h = bh & 15;
#pragma unroll
    for (int mt = 0; mt < 2; mt++) {
#pragma unroll
        for (int half = 0; half < 2; half++) {
            const float inv = 1.f / li[mt * 2 + half];
            const int rg = q0 + wq + (mt << 4) + (half << 3) + r0;
            uint32_t* row = AO + (size_t)(b * SEQ + rg) * DIM + (h << 6);
#pragma unroll
            for (int nt = 0; nt < 8; nt++) {
                *(uint2*)(row + (nt << 3) + (tig << 1)) = make_uint2(
                    f32_tf32(o[mt][nt][half*2] * inv),
                    f32_tf32(o[mt][nt][half*2 + 1] * inv));
            }
        }
    }
}

/* ---------------- launch -------------------------------------------------- */
extern "C" void kernel_launch(void* const* d_in, const int* in_sizes, int n_in,
                              void* d_out, int out_size)
{
    const float* q  = (const float*)d_in[0];
    const float* k  = (const float*)d_in[1];
    const float* v  = (const float*)d_in[2];
    const float* wq = (const float*)d_in[3];
    const float* wk = (const float*)d_in[4];
    const float* wv = (const float*)d_in[5];
    const float* wo = (const float*)d_in[6];

    uint32_t *qt, *kt, *vt, *wqt, *wkt, *wvt, *wot, *qh, *kh, *vh, *ao;
    cudaGetSymbolAddress((void**)&qt,  g_qt);
    cudaGetSymbolAddress((void**)&kt,  g_kt);
    cudaGetSymbolAddress((void**)&vt,  g_vt);
    cudaGetSymbolAddress((void**)&wqt, g_wq);
    cudaGetSymbolAddress((void**)&wkt, g_wk);
    cudaGetSymbolAddress((void**)&wvt, g_wv);
    cudaGetSymbolAddress((void**)&wot, g_wo);
    cudaGetSymbolAddress((void**)&qh,  g_qh);
    cudaGetSymbolAddress((void**)&kh,  g_kh);
    cudaGetSymbolAddress((void**)&vh,  g_vh);
    cudaGetSymbolAddress((void**)&ao,  g_ao);

    const int flash_smem = (8192 + 4096 + 4096 + 8192) * 4;  /* 98304 */
    cudaFuncSetAttribute(gemm_qkv,  cudaFuncAttributeMaxDynamicSharedMemorySize, GEMM_SMEM);
    cudaFuncSetAttribute(gemm_out,  cudaFuncAttributeMaxDynamicSharedMemorySize, GEMM_SMEM);
    cudaFuncSetAttribute(flash_attn, cudaFuncAttributeMaxDynamicSharedMemorySize, flash_smem);

    /* fp32 -> tf32 pre-conversion */
    const int nAct = MROWS * DIM / 4, nW = DIM * DIM / 4;
    cvt_tf32_kernel<<<(nAct + 255) / 256, 256>>>(q,  qt,  nAct);
    cvt_tf32_kernel<<<(nAct + 255) / 256, 256>>>(k,  kt,  nAct);
    cvt_tf32_kernel<<<(nAct + 255) / 256, 256>>>(v,  vt,  nAct);
    cvt_tf32_kernel<<<(nW   + 255) / 256, 256>>>(wq, wqt, nW);
    cvt_tf32_kernel<<<(nW   + 255) / 256, 256>>>(wk, wkt, nW);
    cvt_tf32_kernel<<<(nW   + 255) / 256, 256>>>(wv, wvt, nW);
    cvt_tf32_kernel<<<(nW   + 255) / 256, 256>>>(wo, wot, nW);

    dim3 gqkv(DIM / BN, MROWS / BM, 3);        /* 4 x 32 x 3 */
    gemm_qkv<<<gqkv, 256, GEMM_SMEM>>>(qt, kt, vt, wqt, wkt, wvt, qh, kh, vh);

    flash_attn<<<dim3(SEQ / 128, BATCH * NH), 128, flash_smem>>>(qh, kh, vh, ao);

    dim3 gout(DIM / BN, MROWS / BM);           /* 4 x 32 */
    gemm_out<<<gout, 256, GEMM_SMEM>>>(ao, wot, (float*)d_out);
}